// round 4
// baseline (speedup 1.0000x reference)
#include <cuda_runtime.h>

#define BB 4
#define NN 2048
#define MM 2049
#define GG 1024
#define CC 3
#define MMQ (MM*MM)                 // 4198401

typedef unsigned long long u64;

// ---------------- scratch (device globals, zero-initialized at load) --------
// Self-cleaning invariant: pipeline leaves everything back at zero (or fully
// overwrites it each replay), so no init kernel is needed.
__device__ u64   g_bestg[BB*GG];    // ~((distbits<<32)|pred); 0 = unassigned
__device__ int   g_nmax[BB];
__device__ int   g_nearest[BB*NN];  // fully overwritten each run
__device__ int   g_tgtf[BB*NN];     // fully overwritten each run
__device__ float g_lastrow[BB*NN];  // fully overwritten each run
__device__ float g_cd[BB], g_sem[BB];  // atomic-acc, zeroed by writer
__device__ float g_mf[BB], g_mb[BB];   // direct store each run

// pos = position * 0.15 + bias, NO fma contraction (match XLA's separate ops)
__device__ __forceinline__ float posx_of(float p){ return __fadd_rn(__fmul_rn(p,0.15f), -29.925f); }
__device__ __forceinline__ float posy_of(float p){ return __fadd_rn(__fmul_rn(p,0.15f), -14.925f); }

__device__ __forceinline__ float pdist(float ax,float ay,float bx,float by){
    float dx = __fsub_rn(ax,bx), dy = __fsub_rn(ay,by);
    float d2 = __fadd_rn(__fmul_rn(dx,dx), __fmul_rn(dy,dy));
    return sqrtf(d2);
}

// ================= K1: nearest gt per prediction (8 lanes/pred) ============
__global__ void k1_nearest(const float* __restrict__ positions,
                           const float* __restrict__ gt_pts,
                           const int*   __restrict__ gt_type,
                           const float* __restrict__ semantics,
                           float* __restrict__ sg_out)
{
    __shared__ float2 spt[GG];
    __shared__ float s_cd, s_sem;
    __shared__ int   s_nm;
    int b     = blockIdx.x >> 6;            // 64 blocks per batch
    int pred0 = (blockIdx.x & 63) * 32;
    int tid   = threadIdx.x;
    if (tid == 0) { s_cd = 0.f; s_sem = 0.f; s_nm = 0; }

    const float2* gp2 = (const float2*)(gt_pts + (size_t)b*GG*2);
    for (int g = tid; g < GG; g += 256) spt[g] = gp2[g];
    __syncthreads();

    int pred = pred0 + (tid >> 3);
    int part = tid & 7;

    float2 praw = ((const float2*)(positions))[b*NN + pred];
    float px = posx_of(praw.x), py = posy_of(praw.y);

    // exact argmin of sqrt(d2) with d2-pruning: sqrt is monotone, so a later
    // candidate with d2<bestd2 but equal rounded sqrt must NOT replace the
    // earlier index -> strict s<bests check preserves jnp.argmin tie rule.
    float bestd2 = 3.4e38f, bests = 3.4e38f; int bestg = 0;
    int g0 = part * (GG/8);
    #pragma unroll 4
    for (int k = 0; k < GG/8; ++k) {
        int g = g0 + k;
        float dx = __fsub_rn(px, spt[g].x), dy = __fsub_rn(py, spt[g].y);
        float d2 = __fadd_rn(__fmul_rn(dx,dx), __fmul_rn(dy,dy));
        if (d2 < bestd2) {
            bestd2 = d2;
            float s = sqrtf(d2);
            if (s < bests) { bests = s; bestg = g; }
        }
    }
    u64 key = ((u64)__float_as_uint(bests) << 32) | (unsigned)bestg;
    #pragma unroll
    for (int o = 4; o; o >>= 1) {
        u64 other = __shfl_down_sync(0xffffffffu, key, o, 8);
        if (other < key) key = other;                 // tie -> smaller g
    }
    if (part == 0) {
        int gb  = (int)(key & 0xffffffffULL);
        float d = __uint_as_float((unsigned)(key >> 32));
        g_nearest[b*NN + pred] = gb;
        atomicMax(&s_nm, gb);
        atomicAdd(&s_cd, d);
        u64 pk = ((u64)__float_as_uint(d) << 32) | (unsigned)pred;
        atomicMax(&g_bestg[b*GG + gb], ~pk);          // min(key) == max(~key)
        int cls = gt_type[b*GG + gb];
        float* sg = sg_out + (size_t)b*CC*NN;
        sg[0*NN + pred] = (cls==0) ? 1.f : 0.f;
        sg[1*NN + pred] = (cls==1) ? 1.f : 0.f;
        sg[2*NN + pred] = (cls==2) ? 1.f : 0.f;
        atomicAdd(&s_sem, semantics[(size_t)b*CC*NN + (size_t)cls*NN + pred]);
    }
    __syncthreads();
    if (tid == 0) {
        atomicAdd(&g_cd[b], s_cd);
        atomicAdd(&g_sem[b], s_sem);
        atomicMax(&g_nmax[b], s_nm);
    }
}

// ===== K2: walk(per-g, smem) + counts/keep + targets + losses. 1 blk/batch ==
__global__ void k2_targets(const int* __restrict__ gt_ins,
                           const float* __restrict__ positions,
                           const float* __restrict__ matches)
{
    __shared__ int s_ins[GG];
    __shared__ int s_bp[GG];      // best pred + 1, 0 = none
    __shared__ int s_nextg[GG];
    __shared__ int s_cnt[NN];
    __shared__ u64 s_keep[NN];    // ~((distbits<<32)|row); 0 = empty
    __shared__ int s_nmax_sh;
    __shared__ float s_red[16];

    int b = blockIdx.x, tid = threadIdx.x;

    for (int g = tid; g < GG; g += 256) {
        s_ins[g] = gt_ins[b*GG + g];
        u64 v = g_bestg[b*GG + g];
        s_bp[g] = v ? (int)((~v) & 0xffffffffULL) + 1 : 0;
        g_bestg[b*GG + g] = 0ULL;                     // self-clean
    }
    for (int i = tid; i < NN; i += 256) { s_cnt[i] = 0; s_keep[i] = 0ULL; }
    if (tid == 0) { s_nmax_sh = g_nmax[b]; g_nmax[b] = 0; }
    __syncthreads();
    int nmaxb = s_nmax_sh;

    // -- phase B: walk once per g (literal jax while_loop, smem-resident) ----
    #pragma unroll
    for (int k = 0; k < 4; ++k) {
        int g = tid + k*256;
        int idx = g, steps = 0, res = -1;
        while (true) {
            bool is_end = (idx >= nmaxb);
            int  gnr    = is_end ? -1 : (idx + 1);
            int  gn     = gnr & (GG-1);
            int  bp     = s_bp[gn];
            bool ex     = (!is_end) && (bp != 0);
            bool same   = (s_ins[idx & (GG-1)] == s_ins[gn]);
            bool matched= ex && same;
            res  = matched ? bp - 1 : -1;
            bool stop = matched || (!same) || (steps >= GG + 2);
            idx = gnr; steps++;
            if (stop) break;
        }
        s_nextg[g] = res;
    }
    __syncthreads();

    // -- phase C: per-pred lookup -> counts + keep (smem atomics) ------------
    int resv[8];
    #pragma unroll
    for (int k = 0; k < 8; ++k) {
        int i = tid + k*256;
        int res = s_nextg[g_nearest[b*NN + i]];
        resv[k] = res;
        if (res >= 0) {
            atomicAdd(&s_cnt[res], 1);
            float2 pi = ((const float2*)positions)[b*NN + i];
            float2 pj = ((const float2*)positions)[b*NN + res];
            float d = pdist(posx_of(pi.x), posy_of(pi.y), posx_of(pj.x), posy_of(pj.y));
            u64 pk = ((u64)__float_as_uint(d) << 32) | (unsigned)i;
            atomicMax(&s_keep[res], ~pk);
        }
    }
    __syncthreads();

    // -- phase D: targets + loss gathers -------------------------------------
    float fsum = 0.f, bsum = 0.f;
    #pragma unroll
    for (int k = 0; k < 8; ++k) {
        int i = tid + k*256;
        int res = resv[k];
        int tgt;
        if (res >= 0) {
            int cnt = s_cnt[res];
            int keeprow = (int)((~s_keep[res]) & 0xffffffffULL);
            tgt = (cnt <= 1 || keeprow == i) ? res : (MM-1);
        } else tgt = MM-1;
        g_tgtf[b*NN + i] = tgt;
        fsum += matches[(size_t)b*MMQ + (size_t)i*MM + tgt];

        int cj = s_cnt[i];
        int tgtb; float lr;
        if (cj == 0) { tgtb = MM-1; lr = 1.f; }
        else { tgtb = (int)((~s_keep[i]) & 0xffffffffULL); lr = 0.f; }
        g_lastrow[b*NN + i] = lr;
        bsum += matches[(size_t)b*MMQ + (size_t)i*MM + tgtb];
    }
    #pragma unroll
    for (int o = 16; o; o >>= 1) {
        fsum += __shfl_xor_sync(0xffffffffu, fsum, o);
        bsum += __shfl_xor_sync(0xffffffffu, bsum, o);
    }
    int wid = tid >> 5;
    if ((tid & 31) == 0) { s_red[wid] = fsum; s_red[8 + wid] = bsum; }
    __syncthreads();
    if (tid == 0) {
        float f = 0.f, bs2 = 0.f;
        #pragma unroll
        for (int w = 0; w < 8; ++w) { f += s_red[w]; bs2 += s_red[8 + w]; }
        g_mf[b] = f; g_mb[b] = bs2;
    }
}

// ================= K3: materialize A (67MB, zeros + ones) + scalars ========
__device__ __forceinline__ float aval(unsigned e) {
    unsigned b = e / (unsigned)MMQ;
    unsigned rem = e - b*(unsigned)MMQ;
    unsigned r = rem / (unsigned)MM;
    unsigned j = rem - r*(unsigned)MM;
    if (r < NN) return (j == (unsigned)g_tgtf[b*NN + r]) ? 1.f : 0.f;
    return (j < NN) ? g_lastrow[b*NN + j] : 0.f;
}

__global__ void k3_write(float* __restrict__ out)
{
    int tid = threadIdx.x;
    float4* vout = (float4*)(out + 4);
    #pragma unroll
    for (int k = 0; k < 4; ++k) {
        unsigned v  = blockIdx.x*1024u + k*256u + tid;   // < 4198400 always
        unsigned e0 = 1u + 4u*v;
        unsigned b  = e0 / (unsigned)MMQ;
        unsigned rem= e0 - b*(unsigned)MMQ;
        unsigned r  = rem / (unsigned)MM;
        unsigned j  = rem - r*(unsigned)MM;
        float4 val = make_float4(0.f,0.f,0.f,0.f);
        if (j + 3 < MM) {                                 // same row, same batch
            if (r < NN) {
                int dj = g_tgtf[b*NN + r] - (int)j;
                val.x = (dj==0)?1.f:0.f; val.y = (dj==1)?1.f:0.f;
                val.z = (dj==2)?1.f:0.f; val.w = (dj==3)?1.f:0.f;
            } else {                                      // r == NN (last row)
                val.x = (j+0 < NN) ? g_lastrow[b*NN + j+0] : 0.f;
                val.y = (j+1 < NN) ? g_lastrow[b*NN + j+1] : 0.f;
                val.z = (j+2 < NN) ? g_lastrow[b*NN + j+2] : 0.f;
                val.w = (j+3 < NN) ? g_lastrow[b*NN + j+3] : 0.f;
            }
        } else {                                          // crosses row/batch
            val.x = aval(e0); val.y = aval(e0+1);
            val.z = aval(e0+2); val.w = aval(e0+3);
        }
        vout[v] = val;
    }

    if (blockIdx.x == 0 && tid == 0) {
        out[3] = aval(0);                                 // head scalar
        out[16793604] = aval(16793601);                   // 3 tail scalars
        out[16793605] = aval(16793602);
        out[16793606] = aval(16793603);
        float cm = 0.f, ml = 0.f, sl = 0.f;
        const float invN = 1.0f / NN;
        #pragma unroll
        for (int b = 0; b < BB; ++b) {
            cm += g_cd[b] * invN;
            sl += -g_sem[b] * invN;
            float lf = -g_mf[b] * invN;
            float lb = -g_mb[b] * invN;
            ml += 0.5f * (lf + lb);
            g_cd[b] = 0.f; g_sem[b] = 0.f;                // self-clean
        }
        const float invB = 1.0f / BB;
        out[0] = cm * invB;
        out[1] = ml * invB;
        out[2] = sl * invB;
    }
}

extern "C" void kernel_launch(void* const* d_in, const int* in_sizes, int n_in,
                              void* d_out, int out_size)
{
    const float* matches   = (const float*)d_in[0];
    const float* positions = (const float*)d_in[1];
    const float* semantics = (const float*)d_in[2];
    /* d_in[3] masks: unused by reference */
    const float* gt_pts    = (const float*)d_in[4];
    const int*   gt_ins    = (const int*)d_in[5];
    const int*   gt_type   = (const int*)d_in[6];

    float* out = (float*)d_out;
    float* sg  = out + 3 + (size_t)BB*MMQ;

    k1_nearest<<<BB*64, 256>>>(positions, gt_pts, gt_type, semantics, sg);
    k2_targets<<<BB, 256>>>(gt_ins, positions, matches);
    k3_write<<<4100, 256>>>(out);   // 4100*256*4 float4 == 4198400 == (B*M*M-4)/4
}

// round 5
// speedup vs baseline: 1.1968x; 1.1968x over previous
#include <cuda_runtime.h>

#define BB 4
#define NN 2048
#define MM 2049
#define GG 1024
#define CC 3
#define MMQ (MM*MM)                 // 4198401

typedef unsigned long long u64;

// ---------------- scratch (device globals, zero-initialized at load) --------
// Self-cleaning invariant: pipeline leaves everything back at zero (or fully
// overwrites it each replay), so no init kernel is needed.
__device__ u64   g_bestg[BB*GG];    // ~((distbits<<32)|pred); 0 = unassigned
__device__ int   g_nmax[BB];
__device__ int   g_nearest[BB*NN];  // fully overwritten each run
__device__ int   g_tgtf[BB*NN];     // fully overwritten each run
__device__ float g_lastrow[BB*NN];  // fully overwritten each run
__device__ float g_cd[BB], g_sem[BB];  // atomic-acc, zeroed by writer
__device__ float g_mf[BB], g_mb[BB];   // direct store each run

// pos = position * 0.15 + bias, NO fma contraction (match XLA's separate ops)
__device__ __forceinline__ float posx_of(float p){ return __fadd_rn(__fmul_rn(p,0.15f), -29.925f); }
__device__ __forceinline__ float posy_of(float p){ return __fadd_rn(__fmul_rn(p,0.15f), -14.925f); }

__device__ __forceinline__ float pdist(float ax,float ay,float bx,float by){
    float dx = __fsub_rn(ax,bx), dy = __fsub_rn(ay,by);
    float d2 = __fadd_rn(__fmul_rn(dx,dx), __fmul_rn(dy,dy));
    return sqrtf(d2);
}

// ================= K1: nearest gt, ONE WARP PER PRED =======================
// 1024 blocks x 256 thr = 8192 warps -> high occupancy. Each lane scans 32
// candidates via 16 LDG.128 (gt_pts: 8KB/batch, L1/L2 resident).
__global__ void __launch_bounds__(256) k1_nearest(
                           const float* __restrict__ positions,
                           const float* __restrict__ gt_pts,
                           const int*   __restrict__ gt_type,
                           const float* __restrict__ semantics,
                           float* __restrict__ sg_out)
{
    __shared__ float s_cd, s_sem;
    __shared__ int   s_nm;
    __shared__ int   s_cls[8];

    int tid  = threadIdx.x;
    int wid  = tid >> 5;
    int lane = tid & 31;
    int pred = blockIdx.x*8 + wid;          // global pred id, 0..BB*NN-1
    int b    = pred >> 11;
    int pi   = pred & (NN-1);

    if (tid == 0) { s_cd = 0.f; s_sem = 0.f; s_nm = 0; }

    float2 praw = ((const float2*)positions)[pred];
    float px = posx_of(praw.x), py = posy_of(praw.y);

    const float4* gp4 = (const float4*)(gt_pts + (size_t)b*GG*2);  // 512 float4

    // exact argmin of sqrt(d2): d2-pruning + lazy sqrt. sqrt monotone =>
    // bests == sqrt(bestd2); skipping non-improving d2 preserves the
    // first-index tie rule of jnp.argmin (candidates visited in ascending g).
    float bestd2 = 3.4e38f, bests = 3.4e38f; int bestg = 0;
    #pragma unroll
    for (int k = 0; k < 16; ++k) {
        float4 f = gp4[k*32 + lane];        // points g0 = 2*(k*32+lane), g0+1
        int g0 = 2*(k*32 + lane);
        {
            float dx = __fsub_rn(px, f.x), dy = __fsub_rn(py, f.y);
            float d2 = __fadd_rn(__fmul_rn(dx,dx), __fmul_rn(dy,dy));
            if (d2 < bestd2) {
                bestd2 = d2;
                float s = sqrtf(d2);
                if (s < bests) { bests = s; bestg = g0; }
            }
        }
        {
            float dx = __fsub_rn(px, f.z), dy = __fsub_rn(py, f.w);
            float d2 = __fadd_rn(__fmul_rn(dx,dx), __fmul_rn(dy,dy));
            if (d2 < bestd2) {
                bestd2 = d2;
                float s = sqrtf(d2);
                if (s < bests) { bests = s; bestg = g0 + 1; }
            }
        }
    }
    u64 key = ((u64)__float_as_uint(bests) << 32) | (unsigned)bestg;
    #pragma unroll
    for (int o = 16; o; o >>= 1) {
        u64 other = __shfl_xor_sync(0xffffffffu, key, o);
        if (other < key) key = other;       // tie -> smaller g (low bits)
    }
    __syncthreads();                        // s_cd/s_sem/s_nm initialized

    if (lane == 0) {
        int gb  = (int)(key & 0xffffffffULL);
        float d = __uint_as_float((unsigned)(key >> 32));
        g_nearest[pred] = gb;
        atomicMax(&s_nm, gb);
        atomicAdd(&s_cd, d);
        u64 pk = ((u64)__float_as_uint(d) << 32) | (unsigned)pi;
        atomicMax(&g_bestg[b*GG + gb], ~pk);          // min(key) == max(~key)
        int cls = gt_type[b*GG + gb];
        s_cls[wid] = cls;
        atomicAdd(&s_sem, semantics[(size_t)b*CC*NN + (size_t)cls*NN + pi]);
    }
    __syncthreads();

    if (tid < 24) {                         // sg: 3 rows x 8 consecutive preds
        int c = tid >> 3, k = tid & 7;
        int p0 = (blockIdx.x & 255)*8;      // pred-in-batch base for this block
        sg_out[(size_t)b*CC*NN + (size_t)c*NN + p0 + k] = (s_cls[k]==c) ? 1.f : 0.f;
    }
    if (tid == 0) {
        atomicAdd(&g_cd[b], s_cd);
        atomicAdd(&g_sem[b], s_sem);
        atomicMax(&g_nmax[b], s_nm);
    }
}

// ===== K2: walk(per-g, smem) + counts/keep + targets + losses. 1 blk/batch ==
__global__ void k2_targets(const int* __restrict__ gt_ins,
                           const float* __restrict__ positions,
                           const float* __restrict__ matches)
{
    __shared__ int s_ins[GG];
    __shared__ int s_bp[GG];      // best pred + 1, 0 = none
    __shared__ int s_nextg[GG];
    __shared__ int s_cnt[NN];
    __shared__ u64 s_keep[NN];    // ~((distbits<<32)|row); 0 = empty
    __shared__ int s_nmax_sh;
    __shared__ float s_red[16];

    int b = blockIdx.x, tid = threadIdx.x;

    for (int g = tid; g < GG; g += 256) {
        s_ins[g] = gt_ins[b*GG + g];
        u64 v = g_bestg[b*GG + g];
        s_bp[g] = v ? (int)((~v) & 0xffffffffULL) + 1 : 0;
        g_bestg[b*GG + g] = 0ULL;                     // self-clean
    }
    for (int i = tid; i < NN; i += 256) { s_cnt[i] = 0; s_keep[i] = 0ULL; }
    if (tid == 0) { s_nmax_sh = g_nmax[b]; g_nmax[b] = 0; }
    __syncthreads();
    int nmaxb = s_nmax_sh;

    // -- phase B: walk once per g (literal jax while_loop, smem-resident) ----
    #pragma unroll
    for (int k = 0; k < 4; ++k) {
        int g = tid + k*256;
        int idx = g, steps = 0, res = -1;
        while (true) {
            bool is_end = (idx >= nmaxb);
            int  gnr    = is_end ? -1 : (idx + 1);
            int  gn     = gnr & (GG-1);
            int  bp     = s_bp[gn];
            bool ex     = (!is_end) && (bp != 0);
            bool same   = (s_ins[idx & (GG-1)] == s_ins[gn]);
            bool matched= ex && same;
            res  = matched ? bp - 1 : -1;
            bool stop = matched || (!same) || (steps >= GG + 2);
            idx = gnr; steps++;
            if (stop) break;
        }
        s_nextg[g] = res;
    }
    __syncthreads();

    // -- phase C: per-pred lookup -> counts + keep (smem atomics) ------------
    int resv[8];
    #pragma unroll
    for (int k = 0; k < 8; ++k) {
        int i = tid + k*256;
        int res = s_nextg[g_nearest[b*NN + i]];
        resv[k] = res;
        if (res >= 0) {
            atomicAdd(&s_cnt[res], 1);
            float2 pi = ((const float2*)positions)[b*NN + i];
            float2 pj = ((const float2*)positions)[b*NN + res];
            float d = pdist(posx_of(pi.x), posy_of(pi.y), posx_of(pj.x), posy_of(pj.y));
            u64 pk = ((u64)__float_as_uint(d) << 32) | (unsigned)i;
            atomicMax(&s_keep[res], ~pk);
        }
    }
    __syncthreads();

    // -- phase D: targets + loss gathers -------------------------------------
    float fsum = 0.f, bsum = 0.f;
    #pragma unroll
    for (int k = 0; k < 8; ++k) {
        int i = tid + k*256;
        int res = resv[k];
        int tgt;
        if (res >= 0) {
            int cnt = s_cnt[res];
            int keeprow = (int)((~s_keep[res]) & 0xffffffffULL);
            tgt = (cnt <= 1 || keeprow == i) ? res : (MM-1);
        } else tgt = MM-1;
        g_tgtf[b*NN + i] = tgt;
        fsum += matches[(size_t)b*MMQ + (size_t)i*MM + tgt];

        int cj = s_cnt[i];
        int tgtb; float lr;
        if (cj == 0) { tgtb = MM-1; lr = 1.f; }
        else { tgtb = (int)((~s_keep[i]) & 0xffffffffULL); lr = 0.f; }
        g_lastrow[b*NN + i] = lr;
        bsum += matches[(size_t)b*MMQ + (size_t)i*MM + tgtb];
    }
    #pragma unroll
    for (int o = 16; o; o >>= 1) {
        fsum += __shfl_xor_sync(0xffffffffu, fsum, o);
        bsum += __shfl_xor_sync(0xffffffffu, bsum, o);
    }
    int wid = tid >> 5;
    if ((tid & 31) == 0) { s_red[wid] = fsum; s_red[8 + wid] = bsum; }
    __syncthreads();
    if (tid == 0) {
        float f = 0.f, bs2 = 0.f;
        #pragma unroll
        for (int w = 0; w < 8; ++w) { f += s_red[w]; bs2 += s_red[8 + w]; }
        g_mf[b] = f; g_mb[b] = bs2;
    }
}

// ================= K3: materialize A (67MB, zeros + ones) + scalars ========
__device__ __forceinline__ float aval(unsigned e) {
    unsigned b = e / (unsigned)MMQ;
    unsigned rem = e - b*(unsigned)MMQ;
    unsigned r = rem / (unsigned)MM;
    unsigned j = rem - r*(unsigned)MM;
    if (r < NN) return (j == (unsigned)g_tgtf[b*NN + r]) ? 1.f : 0.f;
    return (j < NN) ? g_lastrow[b*NN + j] : 0.f;
}

__global__ void k3_write(float* __restrict__ out)
{
    int tid = threadIdx.x;
    float4* vout = (float4*)(out + 4);
    #pragma unroll
    for (int k = 0; k < 4; ++k) {
        unsigned v  = blockIdx.x*1024u + k*256u + tid;   // < 4198400 always
        unsigned e0 = 1u + 4u*v;
        unsigned b  = e0 / (unsigned)MMQ;
        unsigned rem= e0 - b*(unsigned)MMQ;
        unsigned r  = rem / (unsigned)MM;
        unsigned j  = rem - r*(unsigned)MM;
        float4 val = make_float4(0.f,0.f,0.f,0.f);
        if (j + 3 < MM) {                                 // same row, same batch
            if (r < NN) {
                int dj = g_tgtf[b*NN + r] - (int)j;
                val.x = (dj==0)?1.f:0.f; val.y = (dj==1)?1.f:0.f;
                val.z = (dj==2)?1.f:0.f; val.w = (dj==3)?1.f:0.f;
            } else {                                      // r == NN (last row)
                val.x = (j+0 < NN) ? g_lastrow[b*NN + j+0] : 0.f;
                val.y = (j+1 < NN) ? g_lastrow[b*NN + j+1] : 0.f;
                val.z = (j+2 < NN) ? g_lastrow[b*NN + j+2] : 0.f;
                val.w = (j+3 < NN) ? g_lastrow[b*NN + j+3] : 0.f;
            }
        } else {                                          // crosses row/batch
            val.x = aval(e0); val.y = aval(e0+1);
            val.z = aval(e0+2); val.w = aval(e0+3);
        }
        vout[v] = val;
    }

    if (blockIdx.x == 0 && tid == 0) {
        out[3] = aval(0);                                 // head scalar
        out[16793604] = aval(16793601);                   // 3 tail scalars
        out[16793605] = aval(16793602);
        out[16793606] = aval(16793603);
        float cm = 0.f, ml = 0.f, sl = 0.f;
        const float invN = 1.0f / NN;
        #pragma unroll
        for (int b = 0; b < BB; ++b) {
            cm += g_cd[b] * invN;
            sl += -g_sem[b] * invN;
            float lf = -g_mf[b] * invN;
            float lb = -g_mb[b] * invN;
            ml += 0.5f * (lf + lb);
            g_cd[b] = 0.f; g_sem[b] = 0.f;                // self-clean
        }
        const float invB = 1.0f / BB;
        out[0] = cm * invB;
        out[1] = ml * invB;
        out[2] = sl * invB;
    }
}

extern "C" void kernel_launch(void* const* d_in, const int* in_sizes, int n_in,
                              void* d_out, int out_size)
{
    const float* matches   = (const float*)d_in[0];
    const float* positions = (const float*)d_in[1];
    const float* semantics = (const float*)d_in[2];
    /* d_in[3] masks: unused by reference */
    const float* gt_pts    = (const float*)d_in[4];
    const int*   gt_ins    = (const int*)d_in[5];
    const int*   gt_type   = (const int*)d_in[6];

    float* out = (float*)d_out;
    float* sg  = out + 3 + (size_t)BB*MMQ;

    k1_nearest<<<BB*NN/8, 256>>>(positions, gt_pts, gt_type, semantics, sg);
    k2_targets<<<BB, 256>>>(gt_ins, positions, matches);
    k3_write<<<4100, 256>>>(out);   // 4100*256*4 float4 == 4198400 == (B*M*M-4)/4
}

// round 7
// speedup vs baseline: 1.5778x; 1.3184x over previous
#include <cuda_runtime.h>

#define BB 4
#define NN 2048
#define MM 2049
#define GG 1024
#define CC 3
#define MMQ (MM*MM)                 // 4198401

typedef unsigned long long u64;

// ---------------- scratch (device globals, zero-initialized at load) --------
// Self-cleaning invariant: pipeline leaves everything back at zero (or fully
// overwrites it each replay), so no init kernel is needed.
__device__ u64   g_bestg[BB*GG];    // ~((distbits<<32)|pred); 0 = unassigned
__device__ int   g_nmax[BB];
__device__ int   g_nearest[BB*NN];  // fully overwritten each run
__device__ int   g_tgtf[BB*NN];     // fully overwritten each run
__device__ int   g_tgtb[BB*NN];     // fully overwritten each run
__device__ float g_cd[BB], g_sem[BB];   // atomic-acc, zeroed by finalize
__device__ float g_mf[BB], g_mb[BB];    // atomic-acc, zeroed by finalize
__device__ unsigned g_ticket;           // zeroed by finalize

// pos = position * 0.15 + bias, NO fma contraction (match XLA's separate ops)
__device__ __forceinline__ float posx_of(float p){ return __fadd_rn(__fmul_rn(p,0.15f), -29.925f); }
__device__ __forceinline__ float posy_of(float p){ return __fadd_rn(__fmul_rn(p,0.15f), -14.925f); }

__device__ __forceinline__ float pdist(float ax,float ay,float bx,float by){
    float dx = __fsub_rn(ax,bx), dy = __fsub_rn(ay,by);
    float d2 = __fadd_rn(__fmul_rn(dx,dx), __fmul_rn(dy,dy));
    return sqrtf(d2);
}

// ===== K1: [blocks 0..1023] nearest-gt (warp/pred)  ++
//           [blocks 1024..5124] zero-fill out[0 .. 3+B*M*M)  ================
#define NBLK 1024                       // BB*NN/8 nearest blocks
#define ZVEC 4198401                    // float4 count of zero region
#define ZBLK 4101                       // ceil(ZVEC/1024)

__global__ void __launch_bounds__(256) k1_zero_nearest(
                           const float* __restrict__ positions,
                           const float* __restrict__ gt_pts,
                           const int*   __restrict__ gt_type,
                           const float* __restrict__ semantics,
                           float* __restrict__ out,
                           float* __restrict__ sg_out)
{
    if (blockIdx.x >= NBLK) {           // ---------- zero blocks ------------
        unsigned zb = blockIdx.x - NBLK;
        float4* vout = (float4*)out;
        #pragma unroll
        for (int k = 0; k < 4; ++k) {
            unsigned v = zb*1024u + k*256u + threadIdx.x;
            if (v < ZVEC) vout[v] = make_float4(0.f,0.f,0.f,0.f);
        }
        if (zb == 0 && threadIdx.x == 0) {
            out[16793604] = 0.f; out[16793605] = 0.f; out[16793606] = 0.f;
        }
        return;
    }

    // ---------------- nearest blocks (scheduled first) ---------------------
    __shared__ float s_cd, s_sem;
    __shared__ int   s_nm;
    __shared__ int   s_cls[8];

    int tid  = threadIdx.x;
    int wid  = tid >> 5;
    int lane = tid & 31;
    int pred = blockIdx.x*8 + wid;      // global pred id, 0..BB*NN-1
    int b    = pred >> 11;
    int pi   = pred & (NN-1);

    if (tid == 0) { s_cd = 0.f; s_sem = 0.f; s_nm = 0; }

    float2 praw = ((const float2*)positions)[pred];
    float px = posx_of(praw.x), py = posy_of(praw.y);

    const float4* gp4 = (const float4*)(gt_pts + (size_t)b*GG*2);  // 512 float4

    // exact argmin of sqrt(d2): d2-pruning + lazy sqrt; preserves jnp.argmin
    // first-index tie rule (sqrt monotone; ascending-g visit; strict <).
    float bestd2 = 3.4e38f, bests = 3.4e38f; int bestg = 0;
    #pragma unroll
    for (int k = 0; k < 16; ++k) {
        float4 f = gp4[k*32 + lane];    // points g0 = 2*(k*32+lane), g0+1
        int g0 = 2*(k*32 + lane);
        {
            float dx = __fsub_rn(px, f.x), dy = __fsub_rn(py, f.y);
            float d2 = __fadd_rn(__fmul_rn(dx,dx), __fmul_rn(dy,dy));
            if (d2 < bestd2) {
                bestd2 = d2;
                float s = sqrtf(d2);
                if (s < bests) { bests = s; bestg = g0; }
            }
        }
        {
            float dx = __fsub_rn(px, f.z), dy = __fsub_rn(py, f.w);
            float d2 = __fadd_rn(__fmul_rn(dx,dx), __fmul_rn(dy,dy));
            if (d2 < bestd2) {
                bestd2 = d2;
                float s = sqrtf(d2);
                if (s < bests) { bests = s; bestg = g0 + 1; }
            }
        }
    }
    u64 key = ((u64)__float_as_uint(bests) << 32) | (unsigned)bestg;
    #pragma unroll
    for (int o = 16; o; o >>= 1) {
        u64 other = __shfl_xor_sync(0xffffffffu, key, o);
        if (other < key) key = other;   // tie -> smaller g (low bits)
    }
    __syncthreads();                    // s_cd/s_sem/s_nm initialized

    if (lane == 0) {
        int gb  = (int)(key & 0xffffffffULL);
        float d = __uint_as_float((unsigned)(key >> 32));
        g_nearest[pred] = gb;
        atomicMax(&s_nm, gb);
        atomicAdd(&s_cd, d);
        u64 pk = ((u64)__float_as_uint(d) << 32) | (unsigned)pi;
        atomicMax(&g_bestg[b*GG + gb], ~pk);          // min(key) == max(~key)
        int cls = gt_type[b*GG + gb];
        s_cls[wid] = cls;
        atomicAdd(&s_sem, semantics[(size_t)b*CC*NN + (size_t)cls*NN + pi]);
    }
    __syncthreads();

    if (tid < 24) {                     // sg: 3 classes x 8 consecutive preds
        int c = tid >> 3, k = tid & 7;
        int p0 = (blockIdx.x & 255)*8;  // pred-in-batch base for this block
        sg_out[(size_t)b*CC*NN + (size_t)c*NN + p0 + k] = (s_cls[k]==c) ? 1.f : 0.f;
    }
    if (tid == 0) {
        atomicAdd(&g_cd[b], s_cd);
        atomicAdd(&g_sem[b], s_sem);
        atomicMax(&g_nmax[b], s_nm);
    }
}

// ===== K2: walk(per-g) + counts/keep + targets. 1 block/batch, smem ========
__global__ void k2_targets(const int* __restrict__ gt_ins,
                           const float* __restrict__ positions)
{
    __shared__ int s_ins[GG];
    __shared__ int s_bp[GG];      // best pred + 1, 0 = none
    __shared__ int s_nextg[GG];
    __shared__ int s_cnt[NN];
    __shared__ u64 s_keep[NN];    // ~((distbits<<32)|row); 0 = empty
    __shared__ int s_nmax_sh;

    int b = blockIdx.x, tid = threadIdx.x;

    for (int g = tid; g < GG; g += 256) {
        s_ins[g] = gt_ins[b*GG + g];
        u64 v = g_bestg[b*GG + g];
        s_bp[g] = v ? (int)((~v) & 0xffffffffULL) + 1 : 0;
        g_bestg[b*GG + g] = 0ULL;                     // self-clean
    }
    for (int i = tid; i < NN; i += 256) { s_cnt[i] = 0; s_keep[i] = 0ULL; }
    if (tid == 0) { s_nmax_sh = g_nmax[b]; g_nmax[b] = 0; }
    __syncthreads();
    int nmaxb = s_nmax_sh;

    // -- phase B: walk once per g (literal jax while_loop, smem-resident) ----
    #pragma unroll
    for (int k = 0; k < 4; ++k) {
        int g = tid + k*256;
        int idx = g, steps = 0, res = -1;
        while (true) {
            bool is_end = (idx >= nmaxb);
            int  gnr    = is_end ? -1 : (idx + 1);
            int  gn     = gnr & (GG-1);
            int  bp     = s_bp[gn];
            bool ex     = (!is_end) && (bp != 0);
            bool same   = (s_ins[idx & (GG-1)] == s_ins[gn]);
            bool matched= ex && same;
            res  = matched ? bp - 1 : -1;
            bool stop = matched || (!same) || (steps >= GG + 2);
            idx = gnr; steps++;
            if (stop) break;
        }
        s_nextg[g] = res;
    }
    __syncthreads();

    // -- phase C: per-pred lookup -> counts + keep (smem atomics) ------------
    int resv[8];
    #pragma unroll
    for (int k = 0; k < 8; ++k) {
        int i = tid + k*256;
        int res = s_nextg[g_nearest[b*NN + i]];
        resv[k] = res;
        if (res >= 0) {
            atomicAdd(&s_cnt[res], 1);
            float2 pi = ((const float2*)positions)[b*NN + i];
            float2 pj = ((const float2*)positions)[b*NN + res];
            float d = pdist(posx_of(pi.x), posy_of(pi.y), posx_of(pj.x), posy_of(pj.y));
            u64 pk = ((u64)__float_as_uint(d) << 32) | (unsigned)i;
            atomicMax(&s_keep[res], ~pk);
        }
    }
    __syncthreads();

    // -- phase D: targets ----------------------------------------------------
    #pragma unroll
    for (int k = 0; k < 8; ++k) {
        int i = tid + k*256;
        int res = resv[k];
        int tgt;
        if (res >= 0) {
            int cnt = s_cnt[res];
            int keeprow = (int)((~s_keep[res]) & 0xffffffffULL);
            tgt = (cnt <= 1 || keeprow == i) ? res : (MM-1);
        } else tgt = MM-1;
        g_tgtf[b*NN + i] = tgt;
        int cj = s_cnt[i];
        g_tgtb[b*NN + i] = (cj == 0) ? (MM-1)
                         : (int)((~s_keep[i]) & 0xffffffffULL);
    }
}

// ===== K3: scatter ones into pre-zeroed A + loss gathers + finalize ========
__global__ void k3_scatter(const float* __restrict__ matches,
                           float* __restrict__ out)
{
    int t = blockIdx.x*blockDim.x + threadIdx.x;      // BB*NN threads
    int b = t >> 11, i = t & (NN-1);
    int tf = g_tgtf[t], tb = g_tgtb[t];
    size_t rowbase = (size_t)b*MMQ + (size_t)i*MM;
    out[3 + rowbase + tf] = 1.0f;                     // row i's single 1
    if (tb == MM-1)                                   // col i empty -> last row
        out[3 + (size_t)b*MMQ + (size_t)NN*MM + i] = 1.0f;

    float fv = matches[rowbase + tf];                 // match[i, tgt_f[i]]
    float bv = matches[rowbase + tb];                 // match[i, tgt_b[i]]
    #pragma unroll
    for (int o = 16; o; o >>= 1) {
        fv += __shfl_xor_sync(0xffffffffu, fv, o);
        bv += __shfl_xor_sync(0xffffffffu, bv, o);
    }
    if ((threadIdx.x & 31) == 0) {                    // b warp-uniform
        atomicAdd(&g_mf[b], fv);
        atomicAdd(&g_mb[b], bv);
    }
    __syncthreads();

    if (threadIdx.x == 0) {
        __threadfence();
        if (atomicAdd(&g_ticket, 1u) == gridDim.x - 1) {   // last block
            float cm = 0.f, ml = 0.f, sl = 0.f;
            const float invN = 1.0f / NN;
            #pragma unroll
            for (int bb = 0; bb < BB; ++bb) {
                cm += g_cd[bb] * invN;
                sl += -g_sem[bb] * invN;
                float lf = -g_mf[bb] * invN;
                float lb = -g_mb[bb] * invN;
                ml += 0.5f * (lf + lb);
                g_cd[bb]=0.f; g_sem[bb]=0.f; g_mf[bb]=0.f; g_mb[bb]=0.f;
            }
            const float invB = 1.0f / BB;
            out[0] = cm * invB;
            out[1] = ml * invB;
            out[2] = sl * invB;
            g_ticket = 0u;                            // self-clean
        }
    }
}

extern "C" void kernel_launch(void* const* d_in, const int* in_sizes, int n_in,
                              void* d_out, int out_size)
{
    const float* matches   = (const float*)d_in[0];
    const float* positions = (const float*)d_in[1];
    const float* semantics = (const float*)d_in[2];
    /* d_in[3] masks: unused by reference */
    const float* gt_pts    = (const float*)d_in[4];
    const int*   gt_ins    = (const int*)d_in[5];
    const int*   gt_type   = (const int*)d_in[6];

    float* out = (float*)d_out;
    float* sg  = out + 3 + (size_t)BB*MMQ;

    k1_zero_nearest<<<NBLK + ZBLK, 256>>>(positions, gt_pts, gt_type,
                                          semantics, out, sg);
    k2_targets<<<BB, 256>>>(gt_ins, positions);
    k3_scatter<<<BB*NN/256, 256>>>(matches, out);
}

// round 8
// speedup vs baseline: 1.8575x; 1.1772x over previous
#include <cuda_runtime.h>

#define BB 4
#define NN 2048
#define MM 2049
#define GG 1024
#define CC 3
#define MMQ (MM*MM)                 // 4198401

typedef unsigned long long u64;

// ---------------- scratch (device globals, zero-initialized at load) --------
// Cleaning schedule (race-free across graph replays):
//   g_bestg  : written K1 (atomicMax), read K2a, cleaned K2b
//   g_nmax   : written K1 (atomicMax), read K2a, cleaned K2b
//   g_cnt/g_keep : written K2b, read K3 (cross-thread), cleaned by NEXT
//                  replay's K1 zero-blocks (run before K2b)
//   g_cd/g_sem/g_mf/g_mb : atomic-acc, cleaned in K3 finalize
//   g_nearest/g_nextg/g_next : fully overwritten every replay
__device__ u64   g_bestg[BB*GG];    // ~((distbits<<32)|pred); 0 = unassigned
__device__ int   g_nmax[BB];
__device__ int   g_nearest[BB*NN];
__device__ int   g_nextg[BB*GG];
__device__ int   g_next[BB*NN];
__device__ int   g_cnt[BB*NN];
__device__ u64   g_keep[BB*NN];     // ~((distbits<<32)|row); 0 = empty
__device__ float g_cd[BB], g_sem[BB];
__device__ float g_mf[BB], g_mb[BB];
__device__ unsigned g_ticket;

// pos = position * 0.15 + bias, NO fma contraction (match XLA's separate ops)
__device__ __forceinline__ float posx_of(float p){ return __fadd_rn(__fmul_rn(p,0.15f), -29.925f); }
__device__ __forceinline__ float posy_of(float p){ return __fadd_rn(__fmul_rn(p,0.15f), -14.925f); }

__device__ __forceinline__ float pdist(float ax,float ay,float bx,float by){
    float dx = __fsub_rn(ax,bx), dy = __fsub_rn(ay,by);
    float d2 = __fadd_rn(__fmul_rn(dx,dx), __fmul_rn(dy,dy));
    return sqrtf(d2);
}

// ===== K1: [blocks 0..1023] nearest-gt (warp/pred)  ++
//           [blocks 1024..5124] zero-fill A region + clean cnt/keep =========
#define NBLK 1024                       // BB*NN/8 nearest blocks
#define ZVEC 4198401                    // float4 count of zero region
#define ZBLK 4101                       // ceil(ZVEC/1024)

__global__ void __launch_bounds__(256) k1_zero_nearest(
                           const float* __restrict__ positions,
                           const float* __restrict__ gt_pts,
                           const int*   __restrict__ gt_type,
                           const float* __restrict__ semantics,
                           float* __restrict__ out,
                           float* __restrict__ sg_out)
{
    if (blockIdx.x >= NBLK) {           // ---------- zero blocks ------------
        unsigned zb = blockIdx.x - NBLK;
        float4* vout = (float4*)out;
        #pragma unroll
        for (int k = 0; k < 4; ++k) {
            unsigned v = zb*1024u + k*256u + threadIdx.x;
            if (v < ZVEC) vout[v] = make_float4(0.f,0.f,0.f,0.f);
        }
        if (zb < 32) {                  // clean cnt/keep for this replay's K2b
            int idx = zb*256 + threadIdx.x;      // covers BB*NN = 8192
            g_cnt[idx] = 0;
            g_keep[idx] = 0ULL;
        }
        if (zb == 0 && threadIdx.x == 0) {
            out[16793604] = 0.f; out[16793605] = 0.f; out[16793606] = 0.f;
        }
        return;
    }

    // ---------------- nearest blocks (scheduled first) ---------------------
    __shared__ float s_cd, s_sem;
    __shared__ int   s_nm;
    __shared__ int   s_cls[8];

    int tid  = threadIdx.x;
    int wid  = tid >> 5;
    int lane = tid & 31;
    int pred = blockIdx.x*8 + wid;      // global pred id, 0..BB*NN-1
    int b    = pred >> 11;
    int pi   = pred & (NN-1);

    if (tid == 0) { s_cd = 0.f; s_sem = 0.f; s_nm = 0; }

    float2 praw = ((const float2*)positions)[pred];
    float px = posx_of(praw.x), py = posy_of(praw.y);

    const float4* gp4 = (const float4*)(gt_pts + (size_t)b*GG*2);  // 512 float4

    // exact argmin of sqrt(d2): d2-pruning + lazy sqrt; preserves jnp.argmin
    // first-index tie rule (sqrt monotone; ascending-g visit; strict <).
    float bestd2 = 3.4e38f, bests = 3.4e38f; int bestg = 0;
    #pragma unroll
    for (int k = 0; k < 16; ++k) {
        float4 f = gp4[k*32 + lane];    // points g0 = 2*(k*32+lane), g0+1
        int g0 = 2*(k*32 + lane);
        {
            float dx = __fsub_rn(px, f.x), dy = __fsub_rn(py, f.y);
            float d2 = __fadd_rn(__fmul_rn(dx,dx), __fmul_rn(dy,dy));
            if (d2 < bestd2) {
                bestd2 = d2;
                float s = sqrtf(d2);
                if (s < bests) { bests = s; bestg = g0; }
            }
        }
        {
            float dx = __fsub_rn(px, f.z), dy = __fsub_rn(py, f.w);
            float d2 = __fadd_rn(__fmul_rn(dx,dx), __fmul_rn(dy,dy));
            if (d2 < bestd2) {
                bestd2 = d2;
                float s = sqrtf(d2);
                if (s < bests) { bests = s; bestg = g0 + 1; }
            }
        }
    }
    u64 key = ((u64)__float_as_uint(bests) << 32) | (unsigned)bestg;
    #pragma unroll
    for (int o = 16; o; o >>= 1) {
        u64 other = __shfl_xor_sync(0xffffffffu, key, o);
        if (other < key) key = other;   // tie -> smaller g (low bits)
    }
    __syncthreads();                    // s_cd/s_sem/s_nm initialized

    if (lane == 0) {
        int gb  = (int)(key & 0xffffffffULL);
        float d = __uint_as_float((unsigned)(key >> 32));
        g_nearest[pred] = gb;
        atomicMax(&s_nm, gb);
        atomicAdd(&s_cd, d);
        u64 pk = ((u64)__float_as_uint(d) << 32) | (unsigned)pi;
        atomicMax(&g_bestg[b*GG + gb], ~pk);          // min(key) == max(~key)
        int cls = gt_type[b*GG + gb];
        s_cls[wid] = cls;
        atomicAdd(&s_sem, semantics[(size_t)b*CC*NN + (size_t)cls*NN + pi]);
    }
    __syncthreads();

    if (tid < 24) {                     // sg: 3 classes x 8 consecutive preds
        int c = tid >> 3, k = tid & 7;
        int p0 = (blockIdx.x & 255)*8;  // pred-in-batch base for this block
        sg_out[(size_t)b*CC*NN + (size_t)c*NN + p0 + k] = (s_cls[k]==c) ? 1.f : 0.f;
    }
    if (tid == 0) {
        atomicAdd(&g_cd[b], s_cd);
        atomicAdd(&g_sem[b], s_sem);
        atomicMax(&g_nmax[b], s_nm);
    }
}

// ===== K2a: walk once per g. 16 blocks (4/batch), batch staged in smem =====
__global__ void __launch_bounds__(256) k2a_walk(const int* __restrict__ gt_ins)
{
    __shared__ int s_ins[GG];
    __shared__ int s_bp[GG];            // best pred + 1, 0 = none

    int b   = blockIdx.x >> 2;
    int g0  = (blockIdx.x & 3) * 256;
    int tid = threadIdx.x;

    for (int g = tid; g < GG; g += 256) {
        s_ins[g] = gt_ins[b*GG + g];
        u64 v = g_bestg[b*GG + g];
        s_bp[g] = v ? (int)((~v) & 0xffffffffULL) + 1 : 0;
    }
    __syncthreads();
    int nmaxb = g_nmax[b];

    int g = g0 + tid;
    int idx = g, steps = 0, res = -1;
    while (true) {                      // literal jax while_loop transcription
        bool is_end = (idx >= nmaxb);
        int  gnr    = is_end ? -1 : (idx + 1);
        int  gn     = gnr & (GG-1);
        int  bp     = s_bp[gn];
        bool ex     = (!is_end) && (bp != 0);
        bool same   = (s_ins[idx & (GG-1)] == s_ins[gn]);
        bool matched= ex && same;
        res  = matched ? bp - 1 : -1;
        bool stop = matched || (!same) || (steps >= GG + 2);
        idx = gnr; steps++;
        if (stop) break;
    }
    g_nextg[b*GG + g] = res;
}

// ===== K2b: per-pred counts + keep (global atomics); clean bestg/nmax ======
__global__ void __launch_bounds__(256) k2b_count(const float* __restrict__ positions)
{
    int t = blockIdx.x*blockDim.x + threadIdx.x;     // BB*NN threads
    int b = t >> 11, i = t & (NN-1);
    int res = g_nextg[b*GG + g_nearest[t]];
    g_next[t] = res;
    if (res >= 0) {
        atomicAdd(&g_cnt[b*NN + res], 1);
        float2 pi = ((const float2*)positions)[t];
        float2 pj = ((const float2*)positions)[b*NN + res];
        float d = pdist(posx_of(pi.x), posy_of(pi.y), posx_of(pj.x), posy_of(pj.y));
        u64 pk = ((u64)__float_as_uint(d) << 32) | (unsigned)i;
        atomicMax(&g_keep[b*NN + res], ~pk);
    }
    if (t < BB*GG) g_bestg[t] = 0ULL;                // self-clean (K2a done)
    if (t < BB)    g_nmax[t]  = 0;
}

// ===== K3: targets + scatter ones + loss gathers + finalize ================
__global__ void __launch_bounds__(256) k3_scatter(const float* __restrict__ matches,
                                                  float* __restrict__ out)
{
    int t = blockIdx.x*blockDim.x + threadIdx.x;     // BB*NN threads
    int b = t >> 11, i = t & (NN-1);
    int res = g_next[t];
    int tf;
    if (res >= 0) {
        int cnt = g_cnt[b*NN + res];
        int keeprow = (int)((~g_keep[b*NN + res]) & 0xffffffffULL);
        tf = (cnt <= 1 || keeprow == i) ? res : (MM-1);
    } else tf = MM-1;

    int cj = g_cnt[t];
    int tb = (cj == 0) ? (MM-1) : (int)((~g_keep[t]) & 0xffffffffULL);

    size_t rowbase = (size_t)b*MMQ + (size_t)i*MM;
    out[3 + rowbase + tf] = 1.0f;                    // row i's single 1
    if (tb == MM-1)                                  // col i empty -> last row
        out[3 + (size_t)b*MMQ + (size_t)NN*MM + i] = 1.0f;

    float fv = matches[rowbase + tf];                // match[i, tgt_f[i]]
    float bv = matches[rowbase + tb];                // match[i, tgt_b[i]]
    #pragma unroll
    for (int o = 16; o; o >>= 1) {
        fv += __shfl_xor_sync(0xffffffffu, fv, o);
        bv += __shfl_xor_sync(0xffffffffu, bv, o);
    }
    if ((threadIdx.x & 31) == 0) {                   // b warp-uniform
        atomicAdd(&g_mf[b], fv);
        atomicAdd(&g_mb[b], bv);
    }
    __syncthreads();

    if (threadIdx.x == 0) {
        __threadfence();
        if (atomicAdd(&g_ticket, 1u) == gridDim.x - 1) {   // last block
            float cm = 0.f, ml = 0.f, sl = 0.f;
            const float invN = 1.0f / NN;
            #pragma unroll
            for (int bb = 0; bb < BB; ++bb) {
                cm += g_cd[bb] * invN;
                sl += -g_sem[bb] * invN;
                float lf = -g_mf[bb] * invN;
                float lb = -g_mb[bb] * invN;
                ml += 0.5f * (lf + lb);
                g_cd[bb]=0.f; g_sem[bb]=0.f; g_mf[bb]=0.f; g_mb[bb]=0.f;
            }
            const float invB = 1.0f / BB;
            out[0] = cm * invB;
            out[1] = ml * invB;
            out[2] = sl * invB;
            g_ticket = 0u;                           // self-clean
        }
    }
}

extern "C" void kernel_launch(void* const* d_in, const int* in_sizes, int n_in,
                              void* d_out, int out_size)
{
    const float* matches   = (const float*)d_in[0];
    const float* positions = (const float*)d_in[1];
    const float* semantics = (const float*)d_in[2];
    /* d_in[3] masks: unused by reference */
    const float* gt_pts    = (const float*)d_in[4];
    const int*   gt_ins    = (const int*)d_in[5];
    const int*   gt_type   = (const int*)d_in[6];

    float* out = (float*)d_out;
    float* sg  = out + 3 + (size_t)BB*MMQ;

    k1_zero_nearest<<<NBLK + ZBLK, 256>>>(positions, gt_pts, gt_type,
                                          semantics, out, sg);
    k2a_walk<<<BB*4, 256>>>(gt_ins);
    k2b_count<<<BB*NN/256, 256>>>(positions);
    k3_scatter<<<BB*NN/256, 256>>>(matches, out);
}